// round 14
// baseline (speedup 1.0000x reference)
#include <cuda_runtime.h>
#include <cuda_fp16.h>
#include <cstdint>

// ============================================================================
// PatchMerged: Haar-DWT2 + LayerNorm + Linear fused into one tf32 GEMM over
// RAW x data, classic mma.sync m16n8k8 (base sm_103 PTX target — no tcgen05).
//
// R13 (304.9us) ran at 1 CTA/SM: barriers/stats/epilogue serialize with MMA.
// This round halves the CTA N-tile (128x96, 4096 CTAs, 48 accums/thread,
// __launch_bounds__(256,2)) so TWO CTAs fit per SM and overheads hide under
// the other CTA's HMMA stream. A is re-read by the (nhalf 0/1) pair but the
// pair is blockIdx-adjacent -> L2 hit; DRAM unchanged.
//
//   out[row, d] = rstd * (X @ Wf)[row, d] + (-rstd*mu) * S1[d] + S0[d]
//   mu  = 2 * (sum of 'a' samples) / 384          (Haar block is orthonormal)
//   var = (sum x^2 over all 384 raw samples)/384 - mu^2
// ============================================================================

#define NOUT 192
#define KTOT 384
#define NCHUNK 12

// ---- dynamic SMEM layout (bytes) ----
#define A_STAGE  16384          // 128 rows x 128B (16B-granule XOR swizzle)
#define B_STAGE  12288          // 96 rows x 128B
#define SM_A0    0                          // stages 0 / 16384 / 32768
#define SM_B0    49152                      // stages 49152 / 61440 / 73728
#define SM_RED   86016                      // float2 red[128][2] = 2048
#define SM_S1    88064                      // float[192]
#define SM_S0    88832                      // float[192]
#define SM_RSTD  89600                      // float[128]
#define SM_ALPHA 90112                      // float[128]
#define SM_TOTAL 90624

// ---- precomputed weights (recomputed every launch; deterministic) ----
__device__ __align__(16) float g_WfT[NOUT * KTOT];   // [d][k], k=c*4+pos, tf32-rna
__device__ float g_S1[NOUT];
__device__ float g_S0[NOUT];

// ============================================================================
// helpers
// ============================================================================
__device__ __forceinline__ uint32_t s2u(const void* p) {
    uint32_t a;
    asm("{ .reg .u64 t; cvta.to.shared.u64 t, %1; cvt.u32.u64 %0, t; }"
        : "=r"(a) : "l"(p));
    return a;
}
__device__ __forceinline__ void cp_async8(uint32_t s, const void* g) {
    asm volatile("cp.async.ca.shared.global [%0], [%1], 8;" :: "r"(s), "l"(g));
}
__device__ __forceinline__ void cp_async16(uint32_t s, const void* g) {
    asm volatile("cp.async.ca.shared.global [%0], [%1], 16;" :: "r"(s), "l"(g));
}
__device__ __forceinline__ float tf32_rna(float x) {
    float y;
    asm("cvt.rna.tf32.f32 %0, %1;" : "=f"(y) : "f"(x));
    return y;
}
__device__ __forceinline__ uint32_t lds_u32(uint32_t a) {
    uint32_t v;
    asm volatile("ld.shared.b32 %0, [%1];" : "=r"(v) : "r"(a));
    return v;
}
__device__ __forceinline__ float4 lds_f32x4(uint32_t a) {
    float4 v;
    asm volatile("ld.shared.v4.f32 {%0,%1,%2,%3}, [%4];"
                 : "=f"(v.x), "=f"(v.y), "=f"(v.z), "=f"(v.w) : "r"(a));
    return v;
}

#define MMA_TF32(d, a, b0r, b1r)                                            \
    asm volatile(                                                           \
        "mma.sync.aligned.m16n8k8.row.col.f32.tf32.tf32.f32 "               \
        "{%0,%1,%2,%3}, {%4,%5,%6,%7}, {%8,%9}, {%0,%1,%2,%3};"             \
        : "+f"((d)[0]), "+f"((d)[1]), "+f"((d)[2]), "+f"((d)[3])            \
        : "r"((a)[0]), "r"((a)[1]), "r"((a)[2]), "r"((a)[3]),               \
          "r"(b0r), "r"(b1r))

// ============================================================================
// Prep: fold Haar signs + norm_w into WfT (tf32-rna); compute S1, S0.
//   Wf[(c,p), d] = 0.5 * sum_q sign[q][p] * norm_w[q*96+c] * w_red[q*96+c, d]
//   S1[d] = sum_j norm_w[j]*w_red[j,d];  S0[d] = sum_j norm_b[j]*w_red[j,d]
// ============================================================================
__global__ void prep_wfold(const float* __restrict__ nw, const float* __restrict__ w) {
    int c = blockIdx.x;    // 0..95
    int d = threadIdx.x;   // 0..191
    float w0 = nw[0 * 96 + c] * w[(0 * 96 + c) * NOUT + d];
    float w1 = nw[1 * 96 + c] * w[(1 * 96 + c) * NOUT + d];
    float w2 = nw[2 * 96 + c] * w[(2 * 96 + c) * NOUT + d];
    float w3 = nw[3 * 96 + c] * w[(3 * 96 + c) * NOUT + d];
    float* dst = &g_WfT[d * KTOT + c * 4];
    dst[0] = tf32_rna(0.5f * (w0 + w1 + w2 + w3));   // pos a (h0,w0)
    dst[1] = tf32_rna(0.5f * (w0 + w1 - w2 - w3));   // pos b (h0,w1)
    dst[2] = tf32_rna(0.5f * (w0 - w1 + w2 - w3));   // pos c (h1,w0)
    dst[3] = tf32_rna(0.5f * (w0 - w1 - w2 + w3));   // pos d (h1,w1)
}

__global__ void prep_s(const float* __restrict__ nw, const float* __restrict__ nb,
                       const float* __restrict__ w) {
    int d = threadIdx.x;
    float s1 = 0.f, s0 = 0.f;
    for (int j = 0; j < KTOT; j++) {
        float wv = w[j * NOUT + d];
        s1 += nw[j] * wv;
        s0 += nb[j] * wv;
    }
    g_S1[d] = s1;
    g_S0[d] = s0;
}

// ============================================================================
// Main kernel. CTA = (b, i, nhalf): 128 rows x 96 cols. 8 warps: 2(M) x 4(N),
// warp tile 64x24 = 4x3 m16n8k8 tiles, 48 fp32 accums/thread. 2 CTAs/SM.
// ============================================================================
__global__ void __launch_bounds__(256, 2)
pm_main(const float* __restrict__ x, float* __restrict__ out) {
    extern __shared__ char smem[];
    uint32_t sb = s2u(smem);
    int tid = threadIdx.x, lane = tid & 31, wid = tid >> 5;
    int wm = wid & 1, wn = wid >> 1;       // warp grid 2(M) x 4(N)
    int q = lane >> 2, p = lane & 3;       // quad row / thread-in-quad
    int bx = blockIdx.x;
    int nhalf = bx & 1;                    // N half: cols [nhalf*96, nhalf*96+96)
    int i = (bx >> 1) & 127;
    int b = bx >> 8;
    const float* xb = x + (size_t)b * 96 * 65536 + (size_t)(2 * i) * 256;

    float* S1s = (float*)(smem + SM_S1);
    float* S0s = (float*)(smem + SM_S0);
    if (tid < NOUT) { S1s[tid] = g_S1[tid]; S0s[tid] = g_S0[tid]; }

    // A loader: chunk kc covers channels 8kc..8kc+7. k-in-chunk = cc*4 + pos.
    // (a,b) pair = one 8B word at x[c,2i,2j]; (c,d) pair at x[c,2i+1,2j].
    // SMEM row j = 128B; 16B-granule XOR swizzle: granule g -> g ^ (j&7).
    auto loadChunk = [&](int kc, int stage) {
        uint32_t abase = sb + SM_A0 + (uint32_t)(stage * A_STAGE);
#pragma unroll
        for (int it = 0; it < 8; ++it) {
            int idx = it * 256 + tid;          // 0..2047
            int j = idx & 127;
            int qq = idx >> 7;                 // 0..15
            int cc = qq >> 1, h = qq & 1;
            const float* g = xb + (size_t)(kc * 8 + cc) * 65536 + h * 256 + 2 * j;
            uint32_t off = (uint32_t)(j * 128 + ((cc ^ (j & 7)) << 4) + h * 8);
            cp_async8(abase + off, g);
        }
        uint32_t bbase = sb + SM_B0 + (uint32_t)(stage * B_STAGE);
        const float* g0 = g_WfT + (size_t)(nhalf * 96) * KTOT + kc * 32;
#pragma unroll
        for (int it = 0; it < 3; ++it) {
            int idx = it * 256 + tid;          // 0..767
            int d = idx >> 3, u = idx & 7;     // d in [0,96)
            uint32_t off = (uint32_t)(d * 128 + ((u ^ (d & 7)) << 4));
            cp_async16(bbase + off, g0 + (size_t)d * KTOT + u * 4);
        }
    };

    loadChunk(0, 0);
    asm volatile("cp.async.commit_group;" ::: "memory");
    loadChunk(1, 1);
    asm volatile("cp.async.commit_group;" ::: "memory");

    float acc[4][3][4];
#pragma unroll
    for (int mt = 0; mt < 4; ++mt)
#pragma unroll
        for (int nt = 0; nt < 3; ++nt)
#pragma unroll
            for (int e = 0; e < 4; ++e) acc[mt][nt][e] = 0.f;

    // per-thread fragment base offsets (swizzle term added per k-step)
    uint32_t offA[4], offB[3];
#pragma unroll
    for (int mt = 0; mt < 4; ++mt)
        offA[mt] = (uint32_t)((wm * 64 + mt * 16 + q) * 128 + p * 4);
#pragma unroll
    for (int nt = 0; nt < 3; ++nt)
        offB[nt] = (uint32_t)((wn * 24 + nt * 8 + q) * 128 + p * 4);

    // stats: thread t handles row sr = t>>1, channel half sh = t&1
    float suma = 0.f, ssq = 0.f;
    int sr = tid >> 1, sh = tid & 1;

    for (int n = 0; n < NCHUNK; ++n) {
        if (n < NCHUNK - 1)
            asm volatile("cp.async.wait_group 1;" ::: "memory");   // chunk n landed
        else
            asm volatile("cp.async.wait_group 0;" ::: "memory");
        __syncthreads();   // chunk n visible; readers of stage (n+2)%3 are done
        if (n + 2 < NCHUNK) {
            loadChunk(n + 2, (n + 2) % 3);
            asm volatile("cp.async.commit_group;" ::: "memory");
        }

        uint32_t abase = sb + SM_A0 + (uint32_t)((n % 3) * A_STAGE);
        uint32_t bbase = sb + SM_B0 + (uint32_t)((n % 3) * B_STAGE);

        // ---- stats from landed A chunk (each 16B granule = one channel's abcd)
#pragma unroll
        for (int u = 0; u < 4; ++u) {
            int cc = sh * 4 + u;
            uint32_t a = abase + (uint32_t)(sr * 128 + ((cc ^ (sr & 7)) << 4));
            float4 v = lds_f32x4(a);
            suma += v.x;                                  // 'a' sample
            ssq += v.x * v.x + v.y * v.y + v.z * v.z + v.w * v.w;
        }

        // ---- 4 k8-steps of m16n8k8 tf32 mma (A = raw fp32 bits, HW-truncated)
#pragma unroll
        for (int ks = 0; ks < 4; ++ks) {
            uint32_t sw0 = (uint32_t)(((2 * ks) ^ q) << 4);      // k = 8ks + p
            uint32_t sw1 = (uint32_t)(((2 * ks + 1) ^ q) << 4);  // k = 8ks + 4 + p
            uint32_t bf[3][2];
#pragma unroll
            for (int nt = 0; nt < 3; ++nt) {
                bf[nt][0] = lds_u32(bbase + offB[nt] + sw0);
                bf[nt][1] = lds_u32(bbase + offB[nt] + sw1);
            }
            uint32_t af[4][4];
#pragma unroll
            for (int mt = 0; mt < 4; ++mt) {
                af[mt][0] = lds_u32(abase + offA[mt] + sw0);
                af[mt][1] = lds_u32(abase + offA[mt] + 1024 + sw0);   // row + 8
                af[mt][2] = lds_u32(abase + offA[mt] + sw1);
                af[mt][3] = lds_u32(abase + offA[mt] + 1024 + sw1);
            }
#pragma unroll
            for (int mt = 0; mt < 4; ++mt)
#pragma unroll
                for (int nt = 0; nt < 3; ++nt)
                    MMA_TF32(acc[mt][nt], af[mt], bf[nt][0], bf[nt][1]);
        }
    }

    // ---- LayerNorm stats reduction -> per-row rstd / alpha
    ((float2*)(smem + SM_RED))[sr * 2 + sh] = make_float2(suma, ssq);
    __syncthreads();
    if (tid < 128) {
        float2 p0 = ((float2*)(smem + SM_RED))[tid * 2 + 0];
        float2 p1 = ((float2*)(smem + SM_RED))[tid * 2 + 1];
        float sa = p0.x + p1.x;
        float sq = p0.y + p1.y;
        float mu = sa * (2.0f / 384.0f);
        float var = sq * (1.0f / 384.0f) - mu * mu;
        float rstd = rsqrtf(var + 1e-5f);
        ((float*)(smem + SM_RSTD))[tid] = rstd;
        ((float*)(smem + SM_ALPHA))[tid] = -rstd * mu;
    }
    __syncthreads();

    // ---- epilogue: affine + store (8B stores, 32B-sector aligned per quad)
    const float* rstd_s = (const float*)(smem + SM_RSTD);
    const float* alpha_s = (const float*)(smem + SM_ALPHA);
    // global row block = (b, i); columns offset by nhalf*96
    float* outb = out + ((size_t)b * 16384 + (size_t)i * 128) * NOUT + nhalf * 96;
#pragma unroll
    for (int mt = 0; mt < 4; ++mt) {
        int r0 = wm * 64 + mt * 16 + q;
        int r1 = r0 + 8;
        float rs0 = rstd_s[r0], al0 = alpha_s[r0];
        float rs1 = rstd_s[r1], al1 = alpha_s[r1];
#pragma unroll
        for (int nt = 0; nt < 3; ++nt) {
            int cl = wn * 24 + nt * 8 + 2 * p;          // local col in [0,96)
            int cg = nhalf * 96 + cl;                   // global col for S1/S0
            float s1a = S1s[cg], s1b = S1s[cg + 1];
            float s0a = S0s[cg], s0b = S0s[cg + 1];
            float2 v0, v1;
            v0.x = fmaf(rs0, acc[mt][nt][0], fmaf(al0, s1a, s0a));
            v0.y = fmaf(rs0, acc[mt][nt][1], fmaf(al0, s1b, s0b));
            v1.x = fmaf(rs1, acc[mt][nt][2], fmaf(al1, s1a, s0a));
            v1.y = fmaf(rs1, acc[mt][nt][3], fmaf(al1, s1b, s0b));
            *(float2*)(outb + (size_t)r0 * NOUT + cl) = v0;
            *(float2*)(outb + (size_t)r1 * NOUT + cl) = v1;
        }
    }
}

// ============================================================================
// Launch
// ============================================================================
extern "C" void kernel_launch(void* const* d_in, const int* in_sizes, int n_in,
                              void* d_out, int out_size) {
    const float* x  = (const float*)d_in[0];   // [16, 96, 256, 256]
    const float* nw = (const float*)d_in[1];   // [384]
    const float* nb = (const float*)d_in[2];   // [384]
    const float* w  = (const float*)d_in[3];   // [384, 192]
    float* out = (float*)d_out;                // [16, 16384, 192]
    (void)in_sizes; (void)n_in; (void)out_size;

    prep_wfold<<<96, 192>>>(nw, w);
    prep_s<<<1, 192>>>(nw, nb, w);

    cudaFuncSetAttribute(pm_main, cudaFuncAttributeMaxDynamicSharedMemorySize,
                         SM_TOTAL);
    pm_main<<<4096, 256, SM_TOTAL>>>(x, out);
}

// round 16
// speedup vs baseline: 1.3088x; 1.3088x over previous
#include <cuda_runtime.h>
#include <cstdint>

// ============================================================================
// PatchMerged: Haar-DWT2 + LayerNorm + Linear fused into one tf32 GEMM over
// RAW x data, classic mma.sync m16n8k8 (base sm_103 PTX target — no tcgen05).
//
// R13 (304.9us) = 128x192 CTA tile, 3-stage cp.async ring, 1 sync/chunk.
// This round keeps that tile and adds:
//   - PERSISTENT CTAs (grid = SM count): the chunk ring runs continuously
//     across tile boundaries, so the 2-chunk DRAM prologue is paid once per
//     CTA instead of once per wave (~14 waves x ~1us saved).
//   - Fused parallel prep kernel (was: serial prep_s loop + prep_wfold).
//
//   out[row, d] = rstd * (X @ Wf)[row, d] + (-rstd*mu) * S1[d] + S0[d]
//   mu  = 2 * (sum of 'a' samples) / 384          (Haar block is orthonormal)
//   var = (sum x^2 over all 384 raw samples)/384 - mu^2
// ============================================================================

#define NOUT 192
#define KTOT 384
#define NCHUNK 12
#define NTILES 2048

// ---- dynamic SMEM layout (bytes) ----
#define A_STAGE  16384          // 128 rows x 128B (16B-granule XOR swizzle)
#define B_STAGE  24576          // 192 rows x 128B
#define SM_A0    0                          // stages 0 / 16384 / 32768
#define SM_B0    49152                      // stages 49152 / 73728 / 98304
#define SM_RED   122880                     // float2 red[128][2] = 2048
#define SM_S1    124928                     // float[192]
#define SM_S0    125696                     // float[192]
#define SM_RSTD  126464                     // float[128]
#define SM_ALPHA 126976                     // float[128]
#define SM_TOTAL 127488

// ---- precomputed weights (recomputed every launch; deterministic) ----
__device__ __align__(16) float g_WfT[NOUT * KTOT];   // [d][k], k=c*4+pos, tf32-rna
__device__ float g_S1[NOUT];
__device__ float g_S0[NOUT];

// ============================================================================
// helpers
// ============================================================================
__device__ __forceinline__ uint32_t s2u(const void* p) {
    uint32_t a;
    asm("{ .reg .u64 t; cvta.to.shared.u64 t, %1; cvt.u32.u64 %0, t; }"
        : "=r"(a) : "l"(p));
    return a;
}
__device__ __forceinline__ void cp_async8(uint32_t s, const void* g) {
    asm volatile("cp.async.ca.shared.global [%0], [%1], 8;" :: "r"(s), "l"(g));
}
__device__ __forceinline__ void cp_async16(uint32_t s, const void* g) {
    asm volatile("cp.async.ca.shared.global [%0], [%1], 16;" :: "r"(s), "l"(g));
}
__device__ __forceinline__ float tf32_rna(float x) {
    float y;
    asm("cvt.rna.tf32.f32 %0, %1;" : "=f"(y) : "f"(x));
    return y;
}
__device__ __forceinline__ uint32_t lds_u32(uint32_t a) {
    uint32_t v;
    asm volatile("ld.shared.b32 %0, [%1];" : "=r"(v) : "r"(a));
    return v;
}
__device__ __forceinline__ float4 lds_f32x4(uint32_t a) {
    float4 v;
    asm volatile("ld.shared.v4.f32 {%0,%1,%2,%3}, [%4];"
                 : "=f"(v.x), "=f"(v.y), "=f"(v.z), "=f"(v.w) : "r"(a));
    return v;
}

#define MMA_TF32(d, a, b0r, b1r)                                            \
    asm volatile(                                                           \
        "mma.sync.aligned.m16n8k8.row.col.f32.tf32.tf32.f32 "               \
        "{%0,%1,%2,%3}, {%4,%5,%6,%7}, {%8,%9}, {%0,%1,%2,%3};"             \
        : "+f"((d)[0]), "+f"((d)[1]), "+f"((d)[2]), "+f"((d)[3])            \
        : "r"((a)[0]), "r"((a)[1]), "r"((a)[2]), "r"((a)[3]),               \
          "r"(b0r), "r"(b1r))

// ============================================================================
// Fused prep: one block per output column d. Threads j = LN channel (q*96+c).
//   sh1[j] = norm_w[j]*w[j,d]; sh0[j] = norm_b[j]*w[j,d]
//   fold (threads j<96, j==c): Wf[(c,p),d] from Haar signs of the 4 q values
//   tree-reduce sh1/sh0 -> S1[d], S0[d]
// ============================================================================
__global__ void prep_all(const float* __restrict__ nw, const float* __restrict__ nb,
                         const float* __restrict__ w) {
    int d = blockIdx.x;    // 0..191
    int j = threadIdx.x;   // 0..383
    __shared__ float sh1[384], sh0[384];
    float wv = w[j * NOUT + d];
    sh1[j] = nw[j] * wv;
    sh0[j] = nb[j] * wv;
    __syncthreads();
    if (j < 96) {
        float w0 = sh1[j], w1 = sh1[96 + j], w2 = sh1[192 + j], w3 = sh1[288 + j];
        float* dst = &g_WfT[d * KTOT + j * 4];
        dst[0] = tf32_rna(0.5f * (w0 + w1 + w2 + w3));   // pos a (h0,w0)
        dst[1] = tf32_rna(0.5f * (w0 + w1 - w2 - w3));   // pos b (h0,w1)
        dst[2] = tf32_rna(0.5f * (w0 - w1 + w2 - w3));   // pos c (h1,w0)
        dst[3] = tf32_rna(0.5f * (w0 - w1 - w2 + w3));   // pos d (h1,w1)
    }
    __syncthreads();
    for (int s = 192; s >= 3; s >>= 1) {   // 192,96,48,24,12,6,3
        if (j < s) { sh1[j] += sh1[j + s]; sh0[j] += sh0[j + s]; }
        __syncthreads();
    }
    if (j == 0) {
        g_S1[d] = sh1[0] + sh1[1] + sh1[2];
        g_S0[d] = sh0[0] + sh0[1] + sh0[2];
    }
}

// ============================================================================
// Main kernel (persistent). CTA walks tiles t0, t0+gridDim.x, ... Each tile =
// (b, i): 128 rows x 192 cols. 8 warps: 2(M) x 4(N), warp tile 64x48 = 4x6
// m16n8k8 tiles, 96 fp32 accums/thread. 3-stage ring continuous across tiles.
// ============================================================================
__global__ void __launch_bounds__(256, 1)
pm_main(const float* __restrict__ x, float* __restrict__ out) {
    extern __shared__ char smem[];
    uint32_t sb = s2u(smem);
    int tid = threadIdx.x, lane = tid & 31, wid = tid >> 5;
    int wm = wid & 1, wn = wid >> 1;       // warp grid 2(M) x 4(N)
    int q = lane >> 2, p = lane & 3;       // quad row / thread-in-quad

    float* S1s = (float*)(smem + SM_S1);
    float* S0s = (float*)(smem + SM_S0);
    if (tid < NOUT) { S1s[tid] = g_S1[tid]; S0s[tid] = g_S0[tid]; }

    int t0 = blockIdx.x;
    int stride = gridDim.x;
    int ntiles = (NTILES - 1 - t0) / stride + 1;
    int totc = ntiles * NCHUNK;

    // loadChunk: chunk kc of tile. Channels 8kc..8kc+7, k-in-chunk = cc*4+pos.
    // (a,b) pair = one 8B word at x[c,2i,2j]; (c,d) pair at x[c,2i+1,2j].
    // SMEM row j = 128B; 16B-granule XOR swizzle: granule g -> g ^ (j&7).
    auto loadChunk = [&](int tile, int kc, int stg) {
        const float* xb = x + (size_t)(tile >> 7) * 96 * 65536
                            + (size_t)(2 * (tile & 127)) * 256;
        uint32_t abase = sb + SM_A0 + (uint32_t)(stg * A_STAGE);
#pragma unroll
        for (int it = 0; it < 8; ++it) {
            int idx = it * 256 + tid;          // 0..2047
            int j = idx & 127;
            int qq = idx >> 7;                 // 0..15
            int cc = qq >> 1, h = qq & 1;
            const float* g = xb + (size_t)(kc * 8 + cc) * 65536 + h * 256 + 2 * j;
            uint32_t off = (uint32_t)(j * 128 + ((cc ^ (j & 7)) << 4) + h * 8);
            cp_async8(abase + off, g);
        }
        uint32_t bbase = sb + SM_B0 + (uint32_t)(stg * B_STAGE);
        const float* g0 = g_WfT + kc * 32;
#pragma unroll
        for (int it = 0; it < 6; ++it) {
            int idx = it * 256 + tid;          // 0..1535
            int d = idx >> 3, u = idx & 7;
            uint32_t off = (uint32_t)(d * 128 + ((u ^ (d & 7)) << 4));
            cp_async16(bbase + off, g0 + (size_t)d * KTOT + u * 4);
        }
    };

    loadChunk(t0, 0, 0);
    asm volatile("cp.async.commit_group;" ::: "memory");
    loadChunk(t0, 1, 1);
    asm volatile("cp.async.commit_group;" ::: "memory");

    float acc[4][6][4];
#pragma unroll
    for (int mt = 0; mt < 4; ++mt)
#pragma unroll
        for (int nt = 0; nt < 6; ++nt)
#pragma unroll
            for (int e = 0; e < 4; ++e) acc[mt][nt][e] = 0.f;

    // per-thread fragment base offsets (swizzle term added per k-step)
    uint32_t offA[4], offB[6];
#pragma unroll
    for (int mt = 0; mt < 4; ++mt)
        offA[mt] = (uint32_t)((wm * 64 + mt * 16 + q) * 128 + p * 4);
#pragma unroll
    for (int nt = 0; nt < 6; ++nt)
        offB[nt] = (uint32_t)((wn * 48 + nt * 8 + q) * 128 + p * 4);

    // stats: thread t handles row sr = t>>1, channel half sh = t&1
    float suma = 0.f, ssq = 0.f;
    int sr = tid >> 1, sh = tid & 1;

    const float* rstd_s = (const float*)(smem + SM_RSTD);
    const float* alpha_s = (const float*)(smem + SM_ALPHA);

    int tile = t0;                 // tile currently being computed
    int n = 0, stg = 0;            // chunk-in-tile and its ring stage
    int ptile = t0, pn = 2, pstg = 2;   // prefetch cursor (chunk lc+2)

    for (int lc = 0; lc < totc; ++lc) {
        if (lc < totc - 1)
            asm volatile("cp.async.wait_group 1;" ::: "memory");   // chunk lc landed
        else
            asm volatile("cp.async.wait_group 0;" ::: "memory");
        __syncthreads();   // chunk lc visible; readers of prefetch stage done
        if (lc + 2 < totc) {
            loadChunk(ptile, pn, pstg);
            asm volatile("cp.async.commit_group;" ::: "memory");
            if (++pn == NCHUNK) { pn = 0; ptile += stride; }
            if (++pstg == 3) pstg = 0;
        }

        uint32_t abase = sb + SM_A0 + (uint32_t)(stg * A_STAGE);
        uint32_t bbase = sb + SM_B0 + (uint32_t)(stg * B_STAGE);

        // ---- stats from landed A chunk (each 16B granule = one channel's abcd)
#pragma unroll
        for (int u = 0; u < 4; ++u) {
            int cc = sh * 4 + u;
            uint32_t a = abase + (uint32_t)(sr * 128 + ((cc ^ (sr & 7)) << 4));
            float4 v = lds_f32x4(a);
            suma += v.x;                                  // 'a' sample
            ssq += v.x * v.x + v.y * v.y + v.z * v.z + v.w * v.w;
        }

        // ---- 4 k8-steps of m16n8k8 tf32 mma (A = raw fp32 bits, HW-truncated)
#pragma unroll
        for (int ks = 0; ks < 4; ++ks) {
            uint32_t sw0 = (uint32_t)(((2 * ks) ^ q) << 4);      // k = 8ks + p
            uint32_t sw1 = (uint32_t)(((2 * ks + 1) ^ q) << 4);  // k = 8ks + 4 + p
            uint32_t bf[6][2];
#pragma unroll
            for (int nt = 0; nt < 6; ++nt) {
                bf[nt][0] = lds_u32(bbase + offB[nt] + sw0);
                bf[nt][1] = lds_u32(bbase + offB[nt] + sw1);
            }
            uint32_t af[4][4];
#pragma unroll
            for (int mt = 0; mt < 4; ++mt) {
                af[mt][0] = lds_u32(abase + offA[mt] + sw0);
                af[mt][1] = lds_u32(abase + offA[mt] + 1024 + sw0);   // row + 8
                af[mt][2] = lds_u32(abase + offA[mt] + sw1);
                af[mt][3] = lds_u32(abase + offA[mt] + 1024 + sw1);
            }
#pragma unroll
            for (int mt = 0; mt < 4; ++mt)
#pragma unroll
                for (int nt = 0; nt < 6; ++nt)
                    MMA_TF32(acc[mt][nt], af[mt], bf[nt][0], bf[nt][1]);
        }

        if (++stg == 3) stg = 0;

        if (++n == NCHUNK) {
            n = 0;
            // ================= per-tile epilogue =================
            ((float2*)(smem + SM_RED))[sr * 2 + sh] = make_float2(suma, ssq);
            __syncthreads();
            if (tid < 128) {
                float2 p0 = ((float2*)(smem + SM_RED))[tid * 2 + 0];
                float2 p1 = ((float2*)(smem + SM_RED))[tid * 2 + 1];
                float sa = p0.x + p1.x;
                float sq = p0.y + p1.y;
                float mu = sa * (2.0f / 384.0f);
                float var = sq * (1.0f / 384.0f) - mu * mu;
                float rstd = rsqrtf(var + 1e-5f);
                ((float*)(smem + SM_RSTD))[tid] = rstd;
                ((float*)(smem + SM_ALPHA))[tid] = -rstd * mu;
            }
            __syncthreads();

            float* outb = out + (size_t)tile * 128 * NOUT;
#pragma unroll
            for (int mt = 0; mt < 4; ++mt) {
                int r0 = wm * 64 + mt * 16 + q;
                int r1 = r0 + 8;
                float rs0 = rstd_s[r0], al0 = alpha_s[r0];
                float rs1 = rstd_s[r1], al1 = alpha_s[r1];
#pragma unroll
                for (int nt = 0; nt < 6; ++nt) {
                    int c0 = wn * 48 + nt * 8 + 2 * p;
                    float s1a = S1s[c0], s1b = S1s[c0 + 1];
                    float s0a = S0s[c0], s0b = S0s[c0 + 1];
                    float2 v0, v1;
                    v0.x = fmaf(rs0, acc[mt][nt][0], fmaf(al0, s1a, s0a));
                    v0.y = fmaf(rs0, acc[mt][nt][1], fmaf(al0, s1b, s0b));
                    v1.x = fmaf(rs1, acc[mt][nt][2], fmaf(al1, s1a, s0a));
                    v1.y = fmaf(rs1, acc[mt][nt][3], fmaf(al1, s1b, s0b));
                    *(float2*)(outb + (size_t)r0 * NOUT + c0) = v0;
                    *(float2*)(outb + (size_t)r1 * NOUT + c0) = v1;
                }
            }
            // reset accumulators for next tile
#pragma unroll
            for (int mt = 0; mt < 4; ++mt)
#pragma unroll
                for (int nt = 0; nt < 6; ++nt)
#pragma unroll
                    for (int e = 0; e < 4; ++e) acc[mt][nt][e] = 0.f;
            suma = 0.f; ssq = 0.f;
            tile += stride;
        }
    }
}

// ============================================================================
// Launch
// ============================================================================
extern "C" void kernel_launch(void* const* d_in, const int* in_sizes, int n_in,
                              void* d_out, int out_size) {
    const float* x  = (const float*)d_in[0];   // [16, 96, 256, 256]
    const float* nw = (const float*)d_in[1];   // [384]
    const float* nb = (const float*)d_in[2];   // [384]
    const float* w  = (const float*)d_in[3];   // [384, 192]
    float* out = (float*)d_out;                // [16, 16384, 192]
    (void)in_sizes; (void)n_in; (void)out_size;

    prep_all<<<NOUT, 384>>>(nw, nb, w);

    int dev = 0, nsm = 148;
    cudaGetDevice(&dev);
    cudaDeviceGetAttribute(&nsm, cudaDevAttrMultiProcessorCount, dev);
    if (nsm < 1) nsm = 148;
    if (nsm > NTILES) nsm = NTILES;

    cudaFuncSetAttribute(pm_main, cudaFuncAttributeMaxDynamicSharedMemorySize,
                         SM_TOTAL);
    pm_main<<<nsm, 256, SM_TOTAL>>>(x, out);
}